// round 14
// baseline (speedup 1.0000x reference)
#include <cuda_runtime.h>

#define T_LEN 512
#define INF   32
#define H     64
#define OUTF  32
#define BPB   8
#define NBLK  128
#define NTHR  256             // 8 warps: warps 0-3 = group 0, 4-7 = group 1
#define SH    96              // h row stride; element j at (j>>3)*12 + (j&7)

typedef unsigned long long ull;

#define GBAR(g) asm volatile("bar.sync %0, 128;" :: "r"((g) + 1) : "memory")

__device__ __forceinline__ void fma2(ull& acc, ull a, ull b) {
    asm("fma.rn.f32x2 %0, %1, %2, %3;" : "=l"(acc) : "l"(a), "l"(b), "l"(acc));
}
__device__ __forceinline__ float foldA(ull v) {
    float2 f; asm("mov.b64 {%0, %1}, %2;" : "=f"(f.x), "=f"(f.y) : "l"(v));
    return f.x + f.y;
}
__device__ __forceinline__ float fast_tanh(float x) {
    float e;
    asm("ex2.approx.f32 %0, %1;" : "=f"(e) : "f"(x * 2.8853900817779268f));
    float r;
    asm("rcp.approx.f32 %0, %1;" : "=f"(r) : "f"(e + 1.f));
    return (e - 1.f) * r;
}

// No-select reduce-scatter (slot meanings lane-permuted by kg bits).
__device__ __forceinline__ float2 rscat(const float* r) {
    float t8[8];
#pragma unroll
    for (int i = 0; i < 8; i++)
        t8[i] = r[i] + __shfl_xor_sync(0xffffffffu, r[8 + i], 4);
    float t4[4];
#pragma unroll
    for (int i = 0; i < 4; i++)
        t4[i] = t8[i] + __shfl_xor_sync(0xffffffffu, t8[4 + i], 2);
    float s0 = t4[0] + __shfl_xor_sync(0xffffffffu, t4[2], 1);
    float s1 = t4[1] + __shfl_xor_sync(0xffffffffu, t4[3], 1);
    return make_float2(s0, s1);
}

__global__ void __launch_bounds__(NTHR, 1)
rnn_fused_kernel(const float* __restrict__ x,
                 const float* __restrict__ Wih1, const float* __restrict__ Whh1,
                 const float* __restrict__ bih1, const float* __restrict__ bhh1,
                 const float* __restrict__ Wih2, const float* __restrict__ Whh2,
                 const float* __restrict__ bih2, const float* __restrict__ bhh2,
                 const float* __restrict__ Wfc1, const float* __restrict__ bfc1,
                 const float* __restrict__ Wfc2, const float* __restrict__ bfc2,
                 float* __restrict__ out)
{
    __shared__ float h1s[2][BPB][SH];
    __shared__ float h2s[2][BPB][SH];
    __shared__ float zfc[BPB][H];

    const int tid  = threadIdx.x;
    const int lane = tid & 31;
    const int wrp  = tid >> 5;
    const int grp  = wrp >> 2;          // independent group 0/1
    const int wig  = wrp & 3;
    const int kg   = lane & 7;          // k-slice
    const int jgl  = lane >> 3;         // j-subgroup
    const int j4   = wig * 16 + jgl * 4;
    const int bq   = grp * 4;
    const int kx0  = kg * 4;
    const int kh0  = kg * 8;
    const int bpx  = kg >> 1;           // batch-slot permutation
    const int jpx  = (kg & 1) << 1;     // j-slot permutation

    // ---- weights into registers, j-PERMUTED: acc u covers j = j4 + (u^jpx) ----
    ull w1[4][2], wh1[4][4], w2r[4][4], wh2[4][4];
#pragma unroll
    for (int u = 0; u < 4; u++) {
        const int ju = j4 + (u ^ jpx);
        ulonglong2 a = *(const ulonglong2*)&Wih1[ju * INF + kx0];
        w1[u][0] = a.x; w1[u][1] = a.y;
        ulonglong2 c0 = *(const ulonglong2*)&Whh1[ju * H + kh0];
        ulonglong2 c1 = *(const ulonglong2*)&Whh1[ju * H + kh0 + 4];
        wh1[u][0] = c0.x; wh1[u][1] = c0.y; wh1[u][2] = c1.x; wh1[u][3] = c1.y;
        ulonglong2 d0 = *(const ulonglong2*)&Wih2[ju * H + kh0];
        ulonglong2 d1 = *(const ulonglong2*)&Wih2[ju * H + kh0 + 4];
        w2r[u][0] = d0.x; w2r[u][1] = d0.y; w2r[u][2] = d1.x; w2r[u][3] = d1.y;
        ulonglong2 e0 = *(const ulonglong2*)&Whh2[ju * H + kh0];
        ulonglong2 e1 = *(const ulonglong2*)&Whh2[ju * H + kh0 + 4];
        wh2[u][0] = e0.x; wh2[u][1] = e0.y; wh2[u][2] = e1.x; wh2[u][3] = e1.y;
    }

    // final outputs of this lane: (bB, jB), (bB, jB+1)
    const int bB = bq + (kg >> 1);
    const int jB = wig * 16 + jgl * 4 + 2 * (kg & 1);
    const float bA1x = bih1[jB] + bhh1[jB];
    const float bA1y = bih1[jB + 1] + bhh1[jB + 1];
    const float bA2x = bih2[jB] + bhh2[jB];
    const float bA2y = bih2[jB + 1] + bhh2[jB + 1];
    const int hwB = bB * SH + (jB >> 3) * 12 + (jB & 7);

    // per-slot h row offsets (batch-permuted) and x pointers
    int hoff[4];
    const float* xq[4];
#pragma unroll
    for (int sb = 0; sb < 4; sb++) {
        const int ab = sb ^ bpx;
        hoff[sb] = (bq + ab) * SH + kg * 12;
        xq[sb] = x + (size_t)(blockIdx.x * BPB + bq + ab) * T_LEN * INF + kx0;
    }

    float* const h1b0 = &h1s[0][0][0];
    float* const h1b1 = &h1s[1][0][0];
    float* const h2b0 = &h2s[0][0][0];
    float* const h2b1 = &h2s[1][0][0];

    // zero h state
    for (int i = tid; i < 2 * BPB * SH; i += NTHR) {
        h1b0[i] = 0.f;   // covers h1s[0..1]
        h2b0[i] = 0.f;
    }
    ulonglong2 X0[4], X1[4];
#pragma unroll
    for (int sb = 0; sb < 4; sb++) X0[sb] = *(const ulonglong2*)(xq[sb]);
    __syncthreads();

    // ---------- preamble: h1(0) = tanh(x(0)@W1^T + b1) -> h1s[1] ----------
    {
        float rL[16];
#pragma unroll
        for (int sb = 0; sb < 4; sb++) {
            ull c0 = 0ull, c1 = 0ull, c2 = 0ull, c3 = 0ull;
            const ull xa = X0[sb].x, xb = X0[sb].y;
            fma2(c0, xa, w1[0][0]); fma2(c1, xa, w1[1][0]);
            fma2(c2, xa, w1[2][0]); fma2(c3, xa, w1[3][0]);
            fma2(c0, xb, w1[0][1]); fma2(c1, xb, w1[1][1]);
            fma2(c2, xb, w1[2][1]); fma2(c3, xb, w1[3][1]);
            rL[sb * 4 + 0] = foldA(c0); rL[sb * 4 + 1] = foldA(c1);
            rL[sb * 4 + 2] = foldA(c2); rL[sb * 4 + 3] = foldA(c3);
        }
        float2 v = rscat(rL);
        *(float2*)(h1b1 + hwB) =
            make_float2(fast_tanh(v.x + bA1x), fast_tanh(v.y + bA1y));
    }
#pragma unroll
    for (int sb = 0; sb < 4; sb++)
        X0[sb] = *(const ulonglong2*)(xq[sb] + INF);   // x(1)
    GBAR(grp);

// One timestep: reads h1(t)=H1R, h2(t-1)=H2R; writes h2(t)=H2W, h1(t+1)=H1W.
// Consumes XC = x(t+1), prefetches XN = x(TN).
#define STEP(H1R, H2R, H2W, H1W, XC, XN, TN)                                   \
    do {                                                                       \
        const int tn_ = (TN);                                                  \
        _Pragma("unroll")                                                      \
        for (int sb = 0; sb < 4; sb++)                                         \
            XN[sb] = *(const ulonglong2*)(xq[sb] + (size_t)tn_ * INF);         \
        float rL2[16], rL1[16];                                                \
        _Pragma("unroll")                                                      \
        for (int sb = 0; sb < 4; sb++) {                                       \
            const float* hb1 = (H1R) + hoff[sb];                               \
            const float* hb2 = (H2R) + hoff[sb];                               \
            ulonglong2 p0 = *(const ulonglong2*)hb1;                           \
            ulonglong2 p1 = *(const ulonglong2*)(hb1 + 4);                     \
            ulonglong2 q0 = *(const ulonglong2*)hb2;                           \
            ulonglong2 q1 = *(const ulonglong2*)(hb2 + 4);                     \
            ull a0 = 0ull, a1 = 0ull, a2 = 0ull, a3 = 0ull;                    \
            fma2(a0, p0.x, w2r[0][0]); fma2(a1, p0.x, w2r[1][0]);              \
            fma2(a2, p0.x, w2r[2][0]); fma2(a3, p0.x, w2r[3][0]);              \
            fma2(a0, p0.y, w2r[0][1]); fma2(a1, p0.y, w2r[1][1]);              \
            fma2(a2, p0.y, w2r[2][1]); fma2(a3, p0.y, w2r[3][1]);              \
            fma2(a0, p1.x, w2r[0][2]); fma2(a1, p1.x, w2r[1][2]);              \
            fma2(a2, p1.x, w2r[2][2]); fma2(a3, p1.x, w2r[3][2]);              \
            fma2(a0, p1.y, w2r[0][3]); fma2(a1, p1.y, w2r[1][3]);              \
            fma2(a2, p1.y, w2r[2][3]); fma2(a3, p1.y, w2r[3][3]);              \
            fma2(a0, q0.x, wh2[0][0]); fma2(a1, q0.x, wh2[1][0]);              \
            fma2(a2, q0.x, wh2[2][0]); fma2(a3, q0.x, wh2[3][0]);              \
            fma2(a0, q0.y, wh2[0][1]); fma2(a1, q0.y, wh2[1][1]);              \
            fma2(a2, q0.y, wh2[2][1]); fma2(a3, q0.y, wh2[3][1]);              \
            fma2(a0, q1.x, wh2[0][2]); fma2(a1, q1.x, wh2[1][2]);              \
            fma2(a2, q1.x, wh2[2][2]); fma2(a3, q1.x, wh2[3][2]);              \
            fma2(a0, q1.y, wh2[0][3]); fma2(a1, q1.y, wh2[1][3]);              \
            fma2(a2, q1.y, wh2[2][3]); fma2(a3, q1.y, wh2[3][3]);              \
            rL2[sb * 4 + 0] = foldA(a0); rL2[sb * 4 + 1] = foldA(a1);          \
            rL2[sb * 4 + 2] = foldA(a2); rL2[sb * 4 + 3] = foldA(a3);          \
            ull c0 = 0ull, c1 = 0ull, c2 = 0ull, c3 = 0ull;                    \
            const ull xa = XC[sb].x, xb = XC[sb].y;                            \
            fma2(c0, xa, w1[0][0]); fma2(c1, xa, w1[1][0]);                    \
            fma2(c2, xa, w1[2][0]); fma2(c3, xa, w1[3][0]);                    \
            fma2(c0, xb, w1[0][1]); fma2(c1, xb, w1[1][1]);                    \
            fma2(c2, xb, w1[2][1]); fma2(c3, xb, w1[3][1]);                    \
            fma2(c0, p0.x, wh1[0][0]); fma2(c1, p0.x, wh1[1][0]);              \
            fma2(c2, p0.x, wh1[2][0]); fma2(c3, p0.x, wh1[3][0]);              \
            fma2(c0, p0.y, wh1[0][1]); fma2(c1, p0.y, wh1[1][1]);              \
            fma2(c2, p0.y, wh1[2][1]); fma2(c3, p0.y, wh1[3][1]);              \
            fma2(c0, p1.x, wh1[0][2]); fma2(c1, p1.x, wh1[1][2]);              \
            fma2(c2, p1.x, wh1[2][2]); fma2(c3, p1.x, wh1[3][2]);              \
            fma2(c0, p1.y, wh1[0][3]); fma2(c1, p1.y, wh1[1][3]);              \
            fma2(c2, p1.y, wh1[2][3]); fma2(c3, p1.y, wh1[3][3]);              \
            rL1[sb * 4 + 0] = foldA(c0); rL1[sb * 4 + 1] = foldA(c1);          \
            rL1[sb * 4 + 2] = foldA(c2); rL1[sb * 4 + 3] = foldA(c3);          \
        }                                                                      \
        float2 v2 = rscat(rL2);                                                \
        *(float2*)((H2W) + hwB) =                                              \
            make_float2(fast_tanh(v2.x + bA2x), fast_tanh(v2.y + bA2y));       \
        float2 v1 = rscat(rL1);                                                \
        *(float2*)((H1W) + hwB) =                                              \
            make_float2(fast_tanh(v1.x + bA1x), fast_tanh(v1.y + bA1y));       \
        GBAR(grp);                                                             \
    } while (0)

    for (int t = 0; t < T_LEN; t += 2) {
        const int tnA = (t + 2 < T_LEN) ? t + 2 : T_LEN - 1;
        STEP(h1b1, h2b0, h2b1, h1b0, X0, X1, tnA);
        const int tnB = (t + 3 < T_LEN) ? t + 3 : T_LEN - 1;
        STEP(h1b0, h2b1, h2b0, h1b1, X1, X0, tnB);
    }
    // final h2(511) is in h2s[0]
    __syncthreads();

    // ---------- FC head ----------
    {
        const int j = tid & 63;
        const int brow = tid >> 6;      // 0..3
#pragma unroll
        for (int rep = 0; rep < 2; rep++) {
            const int b = brow + rep * 4;
            float acc = bfc1[j];
#pragma unroll
            for (int c = 0; c < 8; c++) {
                const float* hb = &h2s[0][b][c * 12];
                const float* wr = &Wfc1[j * H + c * 8];
#pragma unroll
                for (int u = 0; u < 8; u++) acc = fmaf(hb[u], wr[u], acc);
            }
            zfc[b][j] = fmaxf(acc, 0.f);
        }
    }
    __syncthreads();
    {
        const int b = tid >> 5;
        const int o = tid & 31;
        float r = bfc2[o];
#pragma unroll
        for (int k = 0; k < H; k += 4) {
            float4 zv = *(const float4*)&zfc[b][k];
            float4 wv = *(const float4*)&Wfc2[o * H + k];
            r = fmaf(zv.x, wv.x, r); r = fmaf(zv.y, wv.y, r);
            r = fmaf(zv.z, wv.z, r); r = fmaf(zv.w, wv.w, r);
        }
        out[(blockIdx.x * BPB + b) * OUTF + o] = r;
    }
}

extern "C" void kernel_launch(void* const* d_in, const int* in_sizes, int n_in,
                              void* d_out, int out_size)
{
    (void)in_sizes; (void)n_in; (void)out_size;
    const float* x    = (const float*)d_in[0];
    const float* Wih1 = (const float*)d_in[1];
    const float* Whh1 = (const float*)d_in[2];
    const float* bih1 = (const float*)d_in[3];
    const float* bhh1 = (const float*)d_in[4];
    const float* Wih2 = (const float*)d_in[5];
    const float* Whh2 = (const float*)d_in[6];
    const float* bih2 = (const float*)d_in[7];
    const float* bhh2 = (const float*)d_in[8];
    const float* Wfc1 = (const float*)d_in[9];
    const float* bfc1 = (const float*)d_in[10];
    const float* Wfc2 = (const float*)d_in[11];
    const float* bfc2 = (const float*)d_in[12];
    float* out = (float*)d_out;

    rnn_fused_kernel<<<NBLK, NTHR>>>(x, Wih1, Whh1, bih1, bhh1,
                                     Wih2, Whh2, bih2, bhh2,
                                     Wfc1, bfc1, Wfc2, bfc2, out);
}

// round 15
// speedup vs baseline: 1.0446x; 1.0446x over previous
#include <cuda_runtime.h>

#define T_LEN 512
#define INF   32
#define H     64
#define OUTF  32
#define BPB   8
#define NBLK  128
#define NTHR  256             // 8 warps: warps 0-3 = group 0, 4-7 = group 1
#define SH    96              // h row stride; element j at (j>>3)*12 + (j&7)

typedef unsigned long long ull;

#define GBAR(g) asm volatile("bar.sync %0, 128;" :: "r"((g) + 1) : "memory")

__device__ __forceinline__ void fma2(ull& acc, ull a, ull b) {
    asm("fma.rn.f32x2 %0, %1, %2, %3;" : "=l"(acc) : "l"(a), "l"(b), "l"(acc));
}
__device__ __forceinline__ float foldA(ull v) {
    float2 f; asm("mov.b64 {%0, %1}, %2;" : "=f"(f.x), "=f"(f.y) : "l"(v));
    return f.x + f.y;
}
__device__ __forceinline__ float fast_tanh(float x) {
    float cx = fminf(fmaxf(x, -15.f), 15.f);
    float e;
    asm("ex2.approx.f32 %0, %1;" : "=f"(e) : "f"(cx * 2.8853900817779268f));
    float r;
    asm("rcp.approx.f32 %0, %1;" : "=f"(r) : "f"(e + 1.f));
    return (e - 1.f) * r;
}

// No-select reduce-scatter (slot meanings lane-permuted by kg bits).
__device__ __forceinline__ float2 rscat(const float* r) {
    float t8[8];
#pragma unroll
    for (int i = 0; i < 8; i++)
        t8[i] = r[i] + __shfl_xor_sync(0xffffffffu, r[8 + i], 4);
    float t4[4];
#pragma unroll
    for (int i = 0; i < 4; i++)
        t4[i] = t8[i] + __shfl_xor_sync(0xffffffffu, t8[4 + i], 2);
    float s0 = t4[0] + __shfl_xor_sync(0xffffffffu, t4[2], 1);
    float s1 = t4[1] + __shfl_xor_sync(0xffffffffu, t4[3], 1);
    return make_float2(s0, s1);
}

__global__ void __launch_bounds__(NTHR, 1)
rnn_fused_kernel(const float* __restrict__ x,
                 const float* __restrict__ Wih1, const float* __restrict__ Whh1,
                 const float* __restrict__ bih1, const float* __restrict__ bhh1,
                 const float* __restrict__ Wih2, const float* __restrict__ Whh2,
                 const float* __restrict__ bih2, const float* __restrict__ bhh2,
                 const float* __restrict__ Wfc1, const float* __restrict__ bfc1,
                 const float* __restrict__ Wfc2, const float* __restrict__ bfc2,
                 float* __restrict__ out)
{
    __shared__ float h1s[2][BPB][SH];
    __shared__ float h2s[2][BPB][SH];
    __shared__ float zfc[BPB][H];

    const int tid  = threadIdx.x;
    const int lane = tid & 31;
    const int wrp  = tid >> 5;
    const int grp  = wrp >> 2;          // independent group 0/1
    const int wig  = wrp & 3;
    const int kg   = lane & 7;          // k-slice
    const int jgl  = lane >> 3;         // j-subgroup
    const int j4   = wig * 16 + jgl * 4;
    const int bq   = grp * 4;
    const int kx0  = kg * 4;
    const int kh0  = kg * 8;
    const int bpx  = kg >> 1;           // batch-slot permutation
    const int jpx  = (kg & 1) << 1;     // j-slot permutation

    // ---- weights into registers, j-PERMUTED: acc u covers j = j4 + (u^jpx) ----
    ull w1[4][2], wh1[4][4], w2r[4][4], wh2[4][4];
#pragma unroll
    for (int u = 0; u < 4; u++) {
        const int ju = j4 + (u ^ jpx);
        ulonglong2 a = *(const ulonglong2*)&Wih1[ju * INF + kx0];
        w1[u][0] = a.x; w1[u][1] = a.y;
        ulonglong2 c0 = *(const ulonglong2*)&Whh1[ju * H + kh0];
        ulonglong2 c1 = *(const ulonglong2*)&Whh1[ju * H + kh0 + 4];
        wh1[u][0] = c0.x; wh1[u][1] = c0.y; wh1[u][2] = c1.x; wh1[u][3] = c1.y;
        ulonglong2 d0 = *(const ulonglong2*)&Wih2[ju * H + kh0];
        ulonglong2 d1 = *(const ulonglong2*)&Wih2[ju * H + kh0 + 4];
        w2r[u][0] = d0.x; w2r[u][1] = d0.y; w2r[u][2] = d1.x; w2r[u][3] = d1.y;
        ulonglong2 e0 = *(const ulonglong2*)&Whh2[ju * H + kh0];
        ulonglong2 e1 = *(const ulonglong2*)&Whh2[ju * H + kh0 + 4];
        wh2[u][0] = e0.x; wh2[u][1] = e0.y; wh2[u][2] = e1.x; wh2[u][3] = e1.y;
    }

    // final outputs of this lane: (bB, jB), (bB, jB+1)
    const int bB = bq + (kg >> 1);
    const int jB = wig * 16 + jgl * 4 + 2 * (kg & 1);
    const float bA1x = bih1[jB] + bhh1[jB];
    const float bA1y = bih1[jB + 1] + bhh1[jB + 1];
    const float bA2x = bih2[jB] + bhh2[jB];
    const float bA2y = bih2[jB + 1] + bhh2[jB + 1];
    const int hwB = bB * SH + (jB >> 3) * 12 + (jB & 7);

    // per-slot h row offsets (batch-permuted) and x pointers
    int hoff[4];
    const float* xq[4];
#pragma unroll
    for (int sb = 0; sb < 4; sb++) {
        const int ab = sb ^ bpx;
        hoff[sb] = (bq + ab) * SH + kg * 12;
        xq[sb] = x + (size_t)(blockIdx.x * BPB + bq + ab) * T_LEN * INF + kx0;
    }

    float* const h1b0 = &h1s[0][0][0];
    float* const h1b1 = &h1s[1][0][0];
    float* const h2b0 = &h2s[0][0][0];
    float* const h2b1 = &h2s[1][0][0];

    // zero h state
    for (int i = tid; i < 2 * BPB * SH; i += NTHR) {
        h1b0[i] = 0.f;   // covers h1s[0..1]
        h2b0[i] = 0.f;
    }
    ulonglong2 X0[4], X1[4];
#pragma unroll
    for (int sb = 0; sb < 4; sb++) X0[sb] = *(const ulonglong2*)(xq[sb]);
    __syncthreads();

    // ---------- preamble: h1(0) = tanh(x(0)@W1^T + b1) -> h1s[1] ----------
    {
        float rL[16];
#pragma unroll
        for (int sb = 0; sb < 4; sb++) {
            ull c0 = 0ull, c1 = 0ull, c2 = 0ull, c3 = 0ull;
            const ull xa = X0[sb].x, xb = X0[sb].y;
            fma2(c0, xa, w1[0][0]); fma2(c1, xa, w1[1][0]);
            fma2(c2, xa, w1[2][0]); fma2(c3, xa, w1[3][0]);
            fma2(c0, xb, w1[0][1]); fma2(c1, xb, w1[1][1]);
            fma2(c2, xb, w1[2][1]); fma2(c3, xb, w1[3][1]);
            rL[sb * 4 + 0] = foldA(c0); rL[sb * 4 + 1] = foldA(c1);
            rL[sb * 4 + 2] = foldA(c2); rL[sb * 4 + 3] = foldA(c3);
        }
        float2 v = rscat(rL);
        *(float2*)(h1b1 + hwB) =
            make_float2(fast_tanh(v.x + bA1x), fast_tanh(v.y + bA1y));
    }
#pragma unroll
    for (int sb = 0; sb < 4; sb++)
        X0[sb] = *(const ulonglong2*)(xq[sb] + INF);   // x(1)
    GBAR(grp);

// One timestep: reads h1(t)=H1R, h2(t-1)=H2R; writes h2(t)=H2W, h1(t+1)=H1W.
// Consumes XC = x(t+1), prefetches XN = x(TN).
#define STEP(H1R, H2R, H2W, H1W, XC, XN, TN)                                   \
    do {                                                                       \
        const int tn_ = (TN);                                                  \
        _Pragma("unroll")                                                      \
        for (int sb = 0; sb < 4; sb++)                                         \
            XN[sb] = *(const ulonglong2*)(xq[sb] + (size_t)tn_ * INF);         \
        float rL2[16], rL1[16];                                                \
        _Pragma("unroll")                                                      \
        for (int sb = 0; sb < 4; sb++) {                                       \
            const float* hb1 = (H1R) + hoff[sb];                               \
            const float* hb2 = (H2R) + hoff[sb];                               \
            ulonglong2 p0 = *(const ulonglong2*)hb1;                           \
            ulonglong2 p1 = *(const ulonglong2*)(hb1 + 4);                     \
            ulonglong2 q0 = *(const ulonglong2*)hb2;                           \
            ulonglong2 q1 = *(const ulonglong2*)(hb2 + 4);                     \
            ull a0 = 0ull, a1 = 0ull, a2 = 0ull, a3 = 0ull;                    \
            fma2(a0, p0.x, w2r[0][0]); fma2(a1, p0.x, w2r[1][0]);              \
            fma2(a2, p0.x, w2r[2][0]); fma2(a3, p0.x, w2r[3][0]);              \
            fma2(a0, p0.y, w2r[0][1]); fma2(a1, p0.y, w2r[1][1]);              \
            fma2(a2, p0.y, w2r[2][1]); fma2(a3, p0.y, w2r[3][1]);              \
            fma2(a0, p1.x, w2r[0][2]); fma2(a1, p1.x, w2r[1][2]);              \
            fma2(a2, p1.x, w2r[2][2]); fma2(a3, p1.x, w2r[3][2]);              \
            fma2(a0, p1.y, w2r[0][3]); fma2(a1, p1.y, w2r[1][3]);              \
            fma2(a2, p1.y, w2r[2][3]); fma2(a3, p1.y, w2r[3][3]);              \
            fma2(a0, q0.x, wh2[0][0]); fma2(a1, q0.x, wh2[1][0]);              \
            fma2(a2, q0.x, wh2[2][0]); fma2(a3, q0.x, wh2[3][0]);              \
            fma2(a0, q0.y, wh2[0][1]); fma2(a1, q0.y, wh2[1][1]);              \
            fma2(a2, q0.y, wh2[2][1]); fma2(a3, q0.y, wh2[3][1]);              \
            fma2(a0, q1.x, wh2[0][2]); fma2(a1, q1.x, wh2[1][2]);              \
            fma2(a2, q1.x, wh2[2][2]); fma2(a3, q1.x, wh2[3][2]);              \
            fma2(a0, q1.y, wh2[0][3]); fma2(a1, q1.y, wh2[1][3]);              \
            fma2(a2, q1.y, wh2[2][3]); fma2(a3, q1.y, wh2[3][3]);              \
            rL2[sb * 4 + 0] = foldA(a0); rL2[sb * 4 + 1] = foldA(a1);          \
            rL2[sb * 4 + 2] = foldA(a2); rL2[sb * 4 + 3] = foldA(a3);          \
            ull c0 = 0ull, c1 = 0ull, c2 = 0ull, c3 = 0ull;                    \
            const ull xa = XC[sb].x, xb = XC[sb].y;                            \
            fma2(c0, xa, w1[0][0]); fma2(c1, xa, w1[1][0]);                    \
            fma2(c2, xa, w1[2][0]); fma2(c3, xa, w1[3][0]);                    \
            fma2(c0, xb, w1[0][1]); fma2(c1, xb, w1[1][1]);                    \
            fma2(c2, xb, w1[2][1]); fma2(c3, xb, w1[3][1]);                    \
            fma2(c0, p0.x, wh1[0][0]); fma2(c1, p0.x, wh1[1][0]);              \
            fma2(c2, p0.x, wh1[2][0]); fma2(c3, p0.x, wh1[3][0]);              \
            fma2(c0, p0.y, wh1[0][1]); fma2(c1, p0.y, wh1[1][1]);              \
            fma2(c2, p0.y, wh1[2][1]); fma2(c3, p0.y, wh1[3][1]);              \
            fma2(c0, p1.x, wh1[0][2]); fma2(c1, p1.x, wh1[1][2]);              \
            fma2(c2, p1.x, wh1[2][2]); fma2(c3, p1.x, wh1[3][2]);              \
            fma2(c0, p1.y, wh1[0][3]); fma2(c1, p1.y, wh1[1][3]);              \
            fma2(c2, p1.y, wh1[2][3]); fma2(c3, p1.y, wh1[3][3]);              \
            rL1[sb * 4 + 0] = foldA(c0); rL1[sb * 4 + 1] = foldA(c1);          \
            rL1[sb * 4 + 2] = foldA(c2); rL1[sb * 4 + 3] = foldA(c3);          \
        }                                                                      \
        float2 v2 = rscat(rL2);                                                \
        *(float2*)((H2W) + hwB) =                                              \
            make_float2(fast_tanh(v2.x + bA2x), fast_tanh(v2.y + bA2y));       \
        float2 v1 = rscat(rL1);                                                \
        *(float2*)((H1W) + hwB) =                                              \
            make_float2(fast_tanh(v1.x + bA1x), fast_tanh(v1.y + bA1y));       \
        GBAR(grp);                                                             \
    } while (0)

    for (int t = 0; t < T_LEN; t += 2) {
        const int tnA = (t + 2 < T_LEN) ? t + 2 : T_LEN - 1;
        STEP(h1b1, h2b0, h2b1, h1b0, X0, X1, tnA);
        const int tnB = (t + 3 < T_LEN) ? t + 3 : T_LEN - 1;
        STEP(h1b0, h2b1, h2b0, h1b1, X1, X0, tnB);
    }
    // final h2(511) is in h2s[0]
    __syncthreads();

    // ---------- FC head ----------
    {
        const int j = tid & 63;
        const int brow = tid >> 6;      // 0..3
#pragma unroll
        for (int rep = 0; rep < 2; rep++) {
            const int b = brow + rep * 4;
            float acc = bfc1[j];
#pragma unroll
            for (int c = 0; c < 8; c++) {
                const float* hb = &h2s[0][b][c * 12];
                const float* wr = &Wfc1[j * H + c * 8];
#pragma unroll
                for (int u = 0; u < 8; u++) acc = fmaf(hb[u], wr[u], acc);
            }
            zfc[b][j] = fmaxf(acc, 0.f);
        }
    }
    __syncthreads();
    {
        const int b = tid >> 5;
        const int o = tid & 31;
        float r = bfc2[o];
#pragma unroll
        for (int k = 0; k < H; k += 4) {
            float4 zv = *(const float4*)&zfc[b][k];
            float4 wv = *(const float4*)&Wfc2[o * H + k];
            r = fmaf(zv.x, wv.x, r); r = fmaf(zv.y, wv.y, r);
            r = fmaf(zv.z, wv.z, r); r = fmaf(zv.w, wv.w, r);
        }
        out[(blockIdx.x * BPB + b) * OUTF + o] = r;
    }
}

extern "C" void kernel_launch(void* const* d_in, const int* in_sizes, int n_in,
                              void* d_out, int out_size)
{
    (void)in_sizes; (void)n_in; (void)out_size;
    const float* x    = (const float*)d_in[0];
    const float* Wih1 = (const float*)d_in[1];
    const float* Whh1 = (const float*)d_in[2];
    const float* bih1 = (const float*)d_in[3];
    const float* bhh1 = (const float*)d_in[4];
    const float* Wih2 = (const float*)d_in[5];
    const float* Whh2 = (const float*)d_in[6];
    const float* bih2 = (const float*)d_in[7];
    const float* bhh2 = (const float*)d_in[8];
    const float* Wfc1 = (const float*)d_in[9];
    const float* bfc1 = (const float*)d_in[10];
    const float* Wfc2 = (const float*)d_in[11];
    const float* bfc2 = (const float*)d_in[12];
    float* out = (float*)d_out;

    rnn_fused_kernel<<<NBLK, NTHR>>>(x, Wih1, Whh1, bih1, bhh1,
                                     Wih2, Whh2, bih2, bhh2,
                                     Wfc1, bfc1, Wfc2, bfc2, out);
}

// round 16
// speedup vs baseline: 1.0448x; 1.0002x over previous
#include <cuda_runtime.h>

#define T_LEN 512
#define INF   32
#define H     64
#define OUTF  32
#define BPB   8
#define NBLK  128
#define NTHR  256             // 8 warps: warps 0-3 = group 0, 4-7 = group 1
#define SH    96              // h row stride; element j at (j>>3)*12 + (j&7)

typedef unsigned long long ull;

#define GBAR(g) asm volatile("bar.sync %0, 128;" :: "r"((g) + 1) : "memory")

__device__ __forceinline__ void fma2(ull& acc, ull a, ull b) {
    asm("fma.rn.f32x2 %0, %1, %2, %3;" : "=l"(acc) : "l"(a), "l"(b), "l"(acc));
}
__device__ __forceinline__ float foldA(ull v) {
    float2 f; asm("mov.b64 {%0, %1}, %2;" : "=f"(f.x), "=f"(f.y) : "l"(v));
    return f.x + f.y;
}
__device__ __forceinline__ float fast_tanh(float x) {
    float cx = fminf(fmaxf(x, -15.f), 15.f);
    float e;
    asm("ex2.approx.f32 %0, %1;" : "=f"(e) : "f"(cx * 2.8853900817779268f));
    float r;
    asm("rcp.approx.f32 %0, %1;" : "=f"(r) : "f"(e + 1.f));
    return (e - 1.f) * r;
}

// No-select reduce-scatter (slot meanings lane-permuted by kg bits).
__device__ __forceinline__ float2 rscat(const float* r) {
    float t8[8];
#pragma unroll
    for (int i = 0; i < 8; i++)
        t8[i] = r[i] + __shfl_xor_sync(0xffffffffu, r[8 + i], 4);
    float t4[4];
#pragma unroll
    for (int i = 0; i < 4; i++)
        t4[i] = t8[i] + __shfl_xor_sync(0xffffffffu, t8[4 + i], 2);
    float s0 = t4[0] + __shfl_xor_sync(0xffffffffu, t4[2], 1);
    float s1 = t4[1] + __shfl_xor_sync(0xffffffffu, t4[3], 1);
    return make_float2(s0, s1);
}

__global__ void __launch_bounds__(NTHR, 1)
rnn_fused_kernel(const float* __restrict__ x,
                 const float* __restrict__ Wih1, const float* __restrict__ Whh1,
                 const float* __restrict__ bih1, const float* __restrict__ bhh1,
                 const float* __restrict__ Wih2, const float* __restrict__ Whh2,
                 const float* __restrict__ bih2, const float* __restrict__ bhh2,
                 const float* __restrict__ Wfc1, const float* __restrict__ bfc1,
                 const float* __restrict__ Wfc2, const float* __restrict__ bfc2,
                 float* __restrict__ out)
{
    __shared__ float h1s[2][BPB][SH];
    __shared__ float h2s[2][BPB][SH];
    __shared__ float zfc[BPB][H];

    const int tid  = threadIdx.x;
    const int lane = tid & 31;
    const int wrp  = tid >> 5;
    const int grp  = wrp >> 2;          // independent group 0/1
    const int wig  = wrp & 3;
    const int kg   = lane & 7;          // k-slice
    const int jgl  = lane >> 3;         // j-subgroup
    const int j4   = wig * 16 + jgl * 4;
    const int bq   = grp * 4;
    const int kx0  = kg * 4;
    const int kh0  = kg * 8;
    const int bpx  = kg >> 1;           // batch-slot permutation
    const int jpx  = (kg & 1) << 1;     // j-slot permutation

    // ---- weights into registers, j-PERMUTED: acc u covers j = j4 + (u^jpx) ----
    ull w1[4][2], wh1[4][4], w2r[4][4], wh2[4][4];
#pragma unroll
    for (int u = 0; u < 4; u++) {
        const int ju = j4 + (u ^ jpx);
        ulonglong2 a = *(const ulonglong2*)&Wih1[ju * INF + kx0];
        w1[u][0] = a.x; w1[u][1] = a.y;
        ulonglong2 c0 = *(const ulonglong2*)&Whh1[ju * H + kh0];
        ulonglong2 c1 = *(const ulonglong2*)&Whh1[ju * H + kh0 + 4];
        wh1[u][0] = c0.x; wh1[u][1] = c0.y; wh1[u][2] = c1.x; wh1[u][3] = c1.y;
        ulonglong2 d0 = *(const ulonglong2*)&Wih2[ju * H + kh0];
        ulonglong2 d1 = *(const ulonglong2*)&Wih2[ju * H + kh0 + 4];
        w2r[u][0] = d0.x; w2r[u][1] = d0.y; w2r[u][2] = d1.x; w2r[u][3] = d1.y;
        ulonglong2 e0 = *(const ulonglong2*)&Whh2[ju * H + kh0];
        ulonglong2 e1 = *(const ulonglong2*)&Whh2[ju * H + kh0 + 4];
        wh2[u][0] = e0.x; wh2[u][1] = e0.y; wh2[u][2] = e1.x; wh2[u][3] = e1.y;
    }

    // final outputs of this lane: (bB, jB), (bB, jB+1)
    const int bB = bq + (kg >> 1);
    const int jB = wig * 16 + jgl * 4 + 2 * (kg & 1);
    const float bA1x = bih1[jB] + bhh1[jB];
    const float bA1y = bih1[jB + 1] + bhh1[jB + 1];
    const float bA2x = bih2[jB] + bhh2[jB];
    const float bA2y = bih2[jB + 1] + bhh2[jB + 1];
    const int hwB = bB * SH + (jB >> 3) * 12 + (jB & 7);

    // per-slot h row offsets (batch-permuted) and x pointers
    int hoff[4];
    const float* xq[4];
#pragma unroll
    for (int sb = 0; sb < 4; sb++) {
        const int ab = sb ^ bpx;
        hoff[sb] = (bq + ab) * SH + kg * 12;
        xq[sb] = x + (size_t)(blockIdx.x * BPB + bq + ab) * T_LEN * INF + kx0;
    }

    float* const h1b0 = &h1s[0][0][0];
    float* const h1b1 = &h1s[1][0][0];
    float* const h2b0 = &h2s[0][0][0];
    float* const h2b1 = &h2s[1][0][0];

    // zero h state
    for (int i = tid; i < 2 * BPB * SH; i += NTHR) {
        h1b0[i] = 0.f;   // covers h1s[0..1]
        h2b0[i] = 0.f;
    }
    ulonglong2 X0[4], X1[4];
#pragma unroll
    for (int sb = 0; sb < 4; sb++) X0[sb] = *(const ulonglong2*)(xq[sb]);
    __syncthreads();

    // ---------- preamble: h1(0) = tanh(x(0)@W1^T + b1) -> h1s[1] ----------
    {
        float rL[16];
#pragma unroll
        for (int sb = 0; sb < 4; sb++) {
            ull c0 = 0ull, c1 = 0ull, c2 = 0ull, c3 = 0ull;
            const ull xa = X0[sb].x, xb = X0[sb].y;
            fma2(c0, xa, w1[0][0]); fma2(c1, xa, w1[1][0]);
            fma2(c2, xa, w1[2][0]); fma2(c3, xa, w1[3][0]);
            fma2(c0, xb, w1[0][1]); fma2(c1, xb, w1[1][1]);
            fma2(c2, xb, w1[2][1]); fma2(c3, xb, w1[3][1]);
            rL[sb * 4 + 0] = foldA(c0); rL[sb * 4 + 1] = foldA(c1);
            rL[sb * 4 + 2] = foldA(c2); rL[sb * 4 + 3] = foldA(c3);
        }
        float2 v = rscat(rL);
        *(float2*)(h1b1 + hwB) =
            make_float2(fast_tanh(v.x + bA1x), fast_tanh(v.y + bA1y));
    }
#pragma unroll
    for (int sb = 0; sb < 4; sb++)
        X0[sb] = *(const ulonglong2*)(xq[sb] + INF);   // x(1)
    GBAR(grp);

// One timestep: reads h1(t)=H1R, h2(t-1)=H2R; writes h2(t)=H2W, h1(t+1)=H1W.
// Consumes XC = x(t+1), prefetches XN = x(TN).
#define STEP(H1R, H2R, H2W, H1W, XC, XN, TN)                                   \
    do {                                                                       \
        const int tn_ = (TN);                                                  \
        _Pragma("unroll")                                                      \
        for (int sb = 0; sb < 4; sb++)                                         \
            XN[sb] = *(const ulonglong2*)(xq[sb] + (size_t)tn_ * INF);         \
        float rL2[16], rL1[16];                                                \
        _Pragma("unroll")                                                      \
        for (int sb = 0; sb < 4; sb++) {                                       \
            const float* hb1 = (H1R) + hoff[sb];                               \
            const float* hb2 = (H2R) + hoff[sb];                               \
            ulonglong2 p0 = *(const ulonglong2*)hb1;                           \
            ulonglong2 p1 = *(const ulonglong2*)(hb1 + 4);                     \
            ulonglong2 q0 = *(const ulonglong2*)hb2;                           \
            ulonglong2 q1 = *(const ulonglong2*)(hb2 + 4);                     \
            ull a0 = 0ull, a1 = 0ull, a2 = 0ull, a3 = 0ull;                    \
            fma2(a0, p0.x, w2r[0][0]); fma2(a1, p0.x, w2r[1][0]);              \
            fma2(a2, p0.x, w2r[2][0]); fma2(a3, p0.x, w2r[3][0]);              \
            fma2(a0, p0.y, w2r[0][1]); fma2(a1, p0.y, w2r[1][1]);              \
            fma2(a2, p0.y, w2r[2][1]); fma2(a3, p0.y, w2r[3][1]);              \
            fma2(a0, p1.x, w2r[0][2]); fma2(a1, p1.x, w2r[1][2]);              \
            fma2(a2, p1.x, w2r[2][2]); fma2(a3, p1.x, w2r[3][2]);              \
            fma2(a0, p1.y, w2r[0][3]); fma2(a1, p1.y, w2r[1][3]);              \
            fma2(a2, p1.y, w2r[2][3]); fma2(a3, p1.y, w2r[3][3]);              \
            fma2(a0, q0.x, wh2[0][0]); fma2(a1, q0.x, wh2[1][0]);              \
            fma2(a2, q0.x, wh2[2][0]); fma2(a3, q0.x, wh2[3][0]);              \
            fma2(a0, q0.y, wh2[0][1]); fma2(a1, q0.y, wh2[1][1]);              \
            fma2(a2, q0.y, wh2[2][1]); fma2(a3, q0.y, wh2[3][1]);              \
            fma2(a0, q1.x, wh2[0][2]); fma2(a1, q1.x, wh2[1][2]);              \
            fma2(a2, q1.x, wh2[2][2]); fma2(a3, q1.x, wh2[3][2]);              \
            fma2(a0, q1.y, wh2[0][3]); fma2(a1, q1.y, wh2[1][3]);              \
            fma2(a2, q1.y, wh2[2][3]); fma2(a3, q1.y, wh2[3][3]);              \
            rL2[sb * 4 + 0] = foldA(a0); rL2[sb * 4 + 1] = foldA(a1);          \
            rL2[sb * 4 + 2] = foldA(a2); rL2[sb * 4 + 3] = foldA(a3);          \
            ull c0 = 0ull, c1 = 0ull, c2 = 0ull, c3 = 0ull;                    \
            const ull xa = XC[sb].x, xb = XC[sb].y;                            \
            fma2(c0, xa, w1[0][0]); fma2(c1, xa, w1[1][0]);                    \
            fma2(c2, xa, w1[2][0]); fma2(c3, xa, w1[3][0]);                    \
            fma2(c0, xb, w1[0][1]); fma2(c1, xb, w1[1][1]);                    \
            fma2(c2, xb, w1[2][1]); fma2(c3, xb, w1[3][1]);                    \
            fma2(c0, p0.x, wh1[0][0]); fma2(c1, p0.x, wh1[1][0]);              \
            fma2(c2, p0.x, wh1[2][0]); fma2(c3, p0.x, wh1[3][0]);              \
            fma2(c0, p0.y, wh1[0][1]); fma2(c1, p0.y, wh1[1][1]);              \
            fma2(c2, p0.y, wh1[2][1]); fma2(c3, p0.y, wh1[3][1]);              \
            fma2(c0, p1.x, wh1[0][2]); fma2(c1, p1.x, wh1[1][2]);              \
            fma2(c2, p1.x, wh1[2][2]); fma2(c3, p1.x, wh1[3][2]);              \
            fma2(c0, p1.y, wh1[0][3]); fma2(c1, p1.y, wh1[1][3]);              \
            fma2(c2, p1.y, wh1[2][3]); fma2(c3, p1.y, wh1[3][3]);              \
            rL1[sb * 4 + 0] = foldA(c0); rL1[sb * 4 + 1] = foldA(c1);          \
            rL1[sb * 4 + 2] = foldA(c2); rL1[sb * 4 + 3] = foldA(c3);          \
        }                                                                      \
        float2 v2 = rscat(rL2);                                                \
        *(float2*)((H2W) + hwB) =                                              \
            make_float2(fast_tanh(v2.x + bA2x), fast_tanh(v2.y + bA2y));       \
        float2 v1 = rscat(rL1);                                                \
        *(float2*)((H1W) + hwB) =                                              \
            make_float2(fast_tanh(v1.x + bA1x), fast_tanh(v1.y + bA1y));       \
        GBAR(grp);                                                             \
    } while (0)

    for (int t = 0; t < T_LEN; t += 2) {
        const int tnA = (t + 2 < T_LEN) ? t + 2 : T_LEN - 1;
        STEP(h1b1, h2b0, h2b1, h1b0, X0, X1, tnA);
        const int tnB = (t + 3 < T_LEN) ? t + 3 : T_LEN - 1;
        STEP(h1b0, h2b1, h2b0, h1b1, X1, X0, tnB);
    }
    // final h2(511) is in h2s[0]
    __syncthreads();

    // ---------- FC head ----------
    {
        const int j = tid & 63;
        const int brow = tid >> 6;      // 0..3
#pragma unroll
        for (int rep = 0; rep < 2; rep++) {
            const int b = brow + rep * 4;
            float acc = bfc1[j];
#pragma unroll
            for (int c = 0; c < 8; c++) {
                const float* hb = &h2s[0][b][c * 12];
                const float* wr = &Wfc1[j * H + c * 8];
#pragma unroll
                for (int u = 0; u < 8; u++) acc = fmaf(hb[u], wr[u], acc);
            }
            zfc[b][j] = fmaxf(acc, 0.f);
        }
    }
    __syncthreads();
    {
        const int b = tid >> 5;
        const int o = tid & 31;
        float r = bfc2[o];
#pragma unroll
        for (int k = 0; k < H; k += 4) {
            float4 zv = *(const float4*)&zfc[b][k];
            float4 wv = *(const float4*)&Wfc2[o * H + k];
            r = fmaf(zv.x, wv.x, r); r = fmaf(zv.y, wv.y, r);
            r = fmaf(zv.z, wv.z, r); r = fmaf(zv.w, wv.w, r);
        }
        out[(blockIdx.x * BPB + b) * OUTF + o] = r;
    }
}

extern "C" void kernel_launch(void* const* d_in, const int* in_sizes, int n_in,
                              void* d_out, int out_size)
{
    (void)in_sizes; (void)n_in; (void)out_size;
    const float* x    = (const float*)d_in[0];
    const float* Wih1 = (const float*)d_in[1];
    const float* Whh1 = (const float*)d_in[2];
    const float* bih1 = (const float*)d_in[3];
    const float* bhh1 = (const float*)d_in[4];
    const float* Wih2 = (const float*)d_in[5];
    const float* Whh2 = (const float*)d_in[6];
    const float* bih2 = (const float*)d_in[7];
    const float* bhh2 = (const float*)d_in[8];
    const float* Wfc1 = (const float*)d_in[9];
    const float* bfc1 = (const float*)d_in[10];
    const float* Wfc2 = (const float*)d_in[11];
    const float* bfc2 = (const float*)d_in[12];
    float* out = (float*)d_out;

    rnn_fused_kernel<<<NBLK, NTHR>>>(x, Wih1, Whh1, bih1, bhh1,
                                     Wih2, Whh2, bih2, bhh2,
                                     Wfc1, bfc1, Wfc2, bfc2, out);
}

// round 17
// speedup vs baseline: 1.0450x; 1.0002x over previous
#include <cuda_runtime.h>

#define T_LEN 512
#define INF   32
#define H     64
#define OUTF  32
#define BPB   8
#define NBLK  128
#define NTHR  256             // 8 warps: warps 0-3 = group 0, 4-7 = group 1
#define SH    96              // h row stride; element j at (j>>3)*12 + (j&7)

typedef unsigned long long ull;

#define GBAR(g) asm volatile("bar.sync %0, 128;" :: "r"((g) + 1) : "memory")

__device__ __forceinline__ void fma2(ull& acc, ull a, ull b) {
    asm("fma.rn.f32x2 %0, %1, %2, %3;" : "=l"(acc) : "l"(a), "l"(b), "l"(acc));
}
__device__ __forceinline__ float foldA(ull v) {
    float2 f; asm("mov.b64 {%0, %1}, %2;" : "=f"(f.x), "=f"(f.y) : "l"(v));
    return f.x + f.y;
}
__device__ __forceinline__ float fast_tanh(float x) {
    float cx = fminf(fmaxf(x, -15.f), 15.f);
    float e;
    asm("ex2.approx.f32 %0, %1;" : "=f"(e) : "f"(cx * 2.8853900817779268f));
    float r;
    asm("rcp.approx.f32 %0, %1;" : "=f"(r) : "f"(e + 1.f));
    return (e - 1.f) * r;
}

// No-select reduce-scatter (slot meanings lane-permuted by kg bits).
__device__ __forceinline__ float2 rscat(const float* r) {
    float t8[8];
#pragma unroll
    for (int i = 0; i < 8; i++)
        t8[i] = r[i] + __shfl_xor_sync(0xffffffffu, r[8 + i], 4);
    float t4[4];
#pragma unroll
    for (int i = 0; i < 4; i++)
        t4[i] = t8[i] + __shfl_xor_sync(0xffffffffu, t8[4 + i], 2);
    float s0 = t4[0] + __shfl_xor_sync(0xffffffffu, t4[2], 1);
    float s1 = t4[1] + __shfl_xor_sync(0xffffffffu, t4[3], 1);
    return make_float2(s0, s1);
}

__global__ void __launch_bounds__(NTHR, 1)
rnn_fused_kernel(const float* __restrict__ x,
                 const float* __restrict__ Wih1, const float* __restrict__ Whh1,
                 const float* __restrict__ bih1, const float* __restrict__ bhh1,
                 const float* __restrict__ Wih2, const float* __restrict__ Whh2,
                 const float* __restrict__ bih2, const float* __restrict__ bhh2,
                 const float* __restrict__ Wfc1, const float* __restrict__ bfc1,
                 const float* __restrict__ Wfc2, const float* __restrict__ bfc2,
                 float* __restrict__ out)
{
    __shared__ float h1s[2][BPB][SH];
    __shared__ float h2s[2][BPB][SH];
    __shared__ float zfc[BPB][H];

    const int tid  = threadIdx.x;
    const int lane = tid & 31;
    const int wrp  = tid >> 5;
    const int grp  = wrp >> 2;          // independent group 0/1
    const int wig  = wrp & 3;
    const int kg   = lane & 7;          // k-slice
    const int jgl  = lane >> 3;         // j-subgroup
    const int j4   = wig * 16 + jgl * 4;
    const int bq   = grp * 4;
    const int kx0  = kg * 4;
    const int kh0  = kg * 8;
    const int bpx  = kg >> 1;           // batch-slot permutation
    const int jpx  = (kg & 1) << 1;     // j-slot permutation

    // ---- weights into registers, j-PERMUTED: acc u covers j = j4 + (u^jpx) ----
    ull w1[4][2], wh1[4][4], w2r[4][4], wh2[4][4];
#pragma unroll
    for (int u = 0; u < 4; u++) {
        const int ju = j4 + (u ^ jpx);
        ulonglong2 a = *(const ulonglong2*)&Wih1[ju * INF + kx0];
        w1[u][0] = a.x; w1[u][1] = a.y;
        ulonglong2 c0 = *(const ulonglong2*)&Whh1[ju * H + kh0];
        ulonglong2 c1 = *(const ulonglong2*)&Whh1[ju * H + kh0 + 4];
        wh1[u][0] = c0.x; wh1[u][1] = c0.y; wh1[u][2] = c1.x; wh1[u][3] = c1.y;
        ulonglong2 d0 = *(const ulonglong2*)&Wih2[ju * H + kh0];
        ulonglong2 d1 = *(const ulonglong2*)&Wih2[ju * H + kh0 + 4];
        w2r[u][0] = d0.x; w2r[u][1] = d0.y; w2r[u][2] = d1.x; w2r[u][3] = d1.y;
        ulonglong2 e0 = *(const ulonglong2*)&Whh2[ju * H + kh0];
        ulonglong2 e1 = *(const ulonglong2*)&Whh2[ju * H + kh0 + 4];
        wh2[u][0] = e0.x; wh2[u][1] = e0.y; wh2[u][2] = e1.x; wh2[u][3] = e1.y;
    }

    // final outputs of this lane: (bB, jB), (bB, jB+1)
    const int bB = bq + (kg >> 1);
    const int jB = wig * 16 + jgl * 4 + 2 * (kg & 1);
    const float bA1x = bih1[jB] + bhh1[jB];
    const float bA1y = bih1[jB + 1] + bhh1[jB + 1];
    const float bA2x = bih2[jB] + bhh2[jB];
    const float bA2y = bih2[jB + 1] + bhh2[jB + 1];
    const int hwB = bB * SH + (jB >> 3) * 12 + (jB & 7);

    // per-slot h row offsets (batch-permuted) and x pointers
    int hoff[4];
    const float* xq[4];
#pragma unroll
    for (int sb = 0; sb < 4; sb++) {
        const int ab = sb ^ bpx;
        hoff[sb] = (bq + ab) * SH + kg * 12;
        xq[sb] = x + (size_t)(blockIdx.x * BPB + bq + ab) * T_LEN * INF + kx0;
    }

    float* const h1b0 = &h1s[0][0][0];
    float* const h1b1 = &h1s[1][0][0];
    float* const h2b0 = &h2s[0][0][0];
    float* const h2b1 = &h2s[1][0][0];

    // zero h state
    for (int i = tid; i < 2 * BPB * SH; i += NTHR) {
        h1b0[i] = 0.f;   // covers h1s[0..1]
        h2b0[i] = 0.f;
    }
    ulonglong2 X0[4], X1[4];
#pragma unroll
    for (int sb = 0; sb < 4; sb++) X0[sb] = *(const ulonglong2*)(xq[sb]);
    __syncthreads();

    // ---------- preamble: h1(0) = tanh(x(0)@W1^T + b1) -> h1s[1] ----------
    {
        float rL[16];
#pragma unroll
        for (int sb = 0; sb < 4; sb++) {
            ull c0 = 0ull, c1 = 0ull, c2 = 0ull, c3 = 0ull;
            const ull xa = X0[sb].x, xb = X0[sb].y;
            fma2(c0, xa, w1[0][0]); fma2(c1, xa, w1[1][0]);
            fma2(c2, xa, w1[2][0]); fma2(c3, xa, w1[3][0]);
            fma2(c0, xb, w1[0][1]); fma2(c1, xb, w1[1][1]);
            fma2(c2, xb, w1[2][1]); fma2(c3, xb, w1[3][1]);
            rL[sb * 4 + 0] = foldA(c0); rL[sb * 4 + 1] = foldA(c1);
            rL[sb * 4 + 2] = foldA(c2); rL[sb * 4 + 3] = foldA(c3);
        }
        float2 v = rscat(rL);
        *(float2*)(h1b1 + hwB) =
            make_float2(fast_tanh(v.x + bA1x), fast_tanh(v.y + bA1y));
    }
#pragma unroll
    for (int sb = 0; sb < 4; sb++)
        X0[sb] = *(const ulonglong2*)(xq[sb] + INF);   // x(1)
    GBAR(grp);

// One timestep: reads h1(t)=H1R, h2(t-1)=H2R; writes h2(t)=H2W, h1(t+1)=H1W.
// Consumes XC = x(t+1), prefetches XN = x(TN).
#define STEP(H1R, H2R, H2W, H1W, XC, XN, TN)                                   \
    do {                                                                       \
        const int tn_ = (TN);                                                  \
        _Pragma("unroll")                                                      \
        for (int sb = 0; sb < 4; sb++)                                         \
            XN[sb] = *(const ulonglong2*)(xq[sb] + (size_t)tn_ * INF);         \
        float rL2[16], rL1[16];                                                \
        _Pragma("unroll")                                                      \
        for (int sb = 0; sb < 4; sb++) {                                       \
            const float* hb1 = (H1R) + hoff[sb];                               \
            const float* hb2 = (H2R) + hoff[sb];                               \
            ulonglong2 p0 = *(const ulonglong2*)hb1;                           \
            ulonglong2 p1 = *(const ulonglong2*)(hb1 + 4);                     \
            ulonglong2 q0 = *(const ulonglong2*)hb2;                           \
            ulonglong2 q1 = *(const ulonglong2*)(hb2 + 4);                     \
            ull a0 = 0ull, a1 = 0ull, a2 = 0ull, a3 = 0ull;                    \
            fma2(a0, p0.x, w2r[0][0]); fma2(a1, p0.x, w2r[1][0]);              \
            fma2(a2, p0.x, w2r[2][0]); fma2(a3, p0.x, w2r[3][0]);              \
            fma2(a0, p0.y, w2r[0][1]); fma2(a1, p0.y, w2r[1][1]);              \
            fma2(a2, p0.y, w2r[2][1]); fma2(a3, p0.y, w2r[3][1]);              \
            fma2(a0, p1.x, w2r[0][2]); fma2(a1, p1.x, w2r[1][2]);              \
            fma2(a2, p1.x, w2r[2][2]); fma2(a3, p1.x, w2r[3][2]);              \
            fma2(a0, p1.y, w2r[0][3]); fma2(a1, p1.y, w2r[1][3]);              \
            fma2(a2, p1.y, w2r[2][3]); fma2(a3, p1.y, w2r[3][3]);              \
            fma2(a0, q0.x, wh2[0][0]); fma2(a1, q0.x, wh2[1][0]);              \
            fma2(a2, q0.x, wh2[2][0]); fma2(a3, q0.x, wh2[3][0]);              \
            fma2(a0, q0.y, wh2[0][1]); fma2(a1, q0.y, wh2[1][1]);              \
            fma2(a2, q0.y, wh2[2][1]); fma2(a3, q0.y, wh2[3][1]);              \
            fma2(a0, q1.x, wh2[0][2]); fma2(a1, q1.x, wh2[1][2]);              \
            fma2(a2, q1.x, wh2[2][2]); fma2(a3, q1.x, wh2[3][2]);              \
            fma2(a0, q1.y, wh2[0][3]); fma2(a1, q1.y, wh2[1][3]);              \
            fma2(a2, q1.y, wh2[2][3]); fma2(a3, q1.y, wh2[3][3]);              \
            rL2[sb * 4 + 0] = foldA(a0); rL2[sb * 4 + 1] = foldA(a1);          \
            rL2[sb * 4 + 2] = foldA(a2); rL2[sb * 4 + 3] = foldA(a3);          \
            ull c0 = 0ull, c1 = 0ull, c2 = 0ull, c3 = 0ull;                    \
            const ull xa = XC[sb].x, xb = XC[sb].y;                            \
            fma2(c0, xa, w1[0][0]); fma2(c1, xa, w1[1][0]);                    \
            fma2(c2, xa, w1[2][0]); fma2(c3, xa, w1[3][0]);                    \
            fma2(c0, xb, w1[0][1]); fma2(c1, xb, w1[1][1]);                    \
            fma2(c2, xb, w1[2][1]); fma2(c3, xb, w1[3][1]);                    \
            fma2(c0, p0.x, wh1[0][0]); fma2(c1, p0.x, wh1[1][0]);              \
            fma2(c2, p0.x, wh1[2][0]); fma2(c3, p0.x, wh1[3][0]);              \
            fma2(c0, p0.y, wh1[0][1]); fma2(c1, p0.y, wh1[1][1]);              \
            fma2(c2, p0.y, wh1[2][1]); fma2(c3, p0.y, wh1[3][1]);              \
            fma2(c0, p1.x, wh1[0][2]); fma2(c1, p1.x, wh1[1][2]);              \
            fma2(c2, p1.x, wh1[2][2]); fma2(c3, p1.x, wh1[3][2]);              \
            fma2(c0, p1.y, wh1[0][3]); fma2(c1, p1.y, wh1[1][3]);              \
            fma2(c2, p1.y, wh1[2][3]); fma2(c3, p1.y, wh1[3][3]);              \
            rL1[sb * 4 + 0] = foldA(c0); rL1[sb * 4 + 1] = foldA(c1);          \
            rL1[sb * 4 + 2] = foldA(c2); rL1[sb * 4 + 3] = foldA(c3);          \
        }                                                                      \
        float2 v2 = rscat(rL2);                                                \
        *(float2*)((H2W) + hwB) =                                              \
            make_float2(fast_tanh(v2.x + bA2x), fast_tanh(v2.y + bA2y));       \
        float2 v1 = rscat(rL1);                                                \
        *(float2*)((H1W) + hwB) =                                              \
            make_float2(fast_tanh(v1.x + bA1x), fast_tanh(v1.y + bA1y));       \
        GBAR(grp);                                                             \
    } while (0)

    for (int t = 0; t < T_LEN; t += 2) {
        const int tnA = (t + 2 < T_LEN) ? t + 2 : T_LEN - 1;
        STEP(h1b1, h2b0, h2b1, h1b0, X0, X1, tnA);
        const int tnB = (t + 3 < T_LEN) ? t + 3 : T_LEN - 1;
        STEP(h1b0, h2b1, h2b0, h1b1, X1, X0, tnB);
    }
    // final h2(511) is in h2s[0]
    __syncthreads();

    // ---------- FC head ----------
    {
        const int j = tid & 63;
        const int brow = tid >> 6;      // 0..3
#pragma unroll
        for (int rep = 0; rep < 2; rep++) {
            const int b = brow + rep * 4;
            float acc = bfc1[j];
#pragma unroll
            for (int c = 0; c < 8; c++) {
                const float* hb = &h2s[0][b][c * 12];
                const float* wr = &Wfc1[j * H + c * 8];
#pragma unroll
                for (int u = 0; u < 8; u++) acc = fmaf(hb[u], wr[u], acc);
            }
            zfc[b][j] = fmaxf(acc, 0.f);
        }
    }
    __syncthreads();
    {
        const int b = tid >> 5;
        const int o = tid & 31;
        float r = bfc2[o];
#pragma unroll
        for (int k = 0; k < H; k += 4) {
            float4 zv = *(const float4*)&zfc[b][k];
            float4 wv = *(const float4*)&Wfc2[o * H + k];
            r = fmaf(zv.x, wv.x, r); r = fmaf(zv.y, wv.y, r);
            r = fmaf(zv.z, wv.z, r); r = fmaf(zv.w, wv.w, r);
        }
        out[(blockIdx.x * BPB + b) * OUTF + o] = r;
    }
}

extern "C" void kernel_launch(void* const* d_in, const int* in_sizes, int n_in,
                              void* d_out, int out_size)
{
    (void)in_sizes; (void)n_in; (void)out_size;
    const float* x    = (const float*)d_in[0];
    const float* Wih1 = (const float*)d_in[1];
    const float* Whh1 = (const float*)d_in[2];
    const float* bih1 = (const float*)d_in[3];
    const float* bhh1 = (const float*)d_in[4];
    const float* Wih2 = (const float*)d_in[5];
    const float* Whh2 = (const float*)d_in[6];
    const float* bih2 = (const float*)d_in[7];
    const float* bhh2 = (const float*)d_in[8];
    const float* Wfc1 = (const float*)d_in[9];
    const float* bfc1 = (const float*)d_in[10];
    const float* Wfc2 = (const float*)d_in[11];
    const float* bfc2 = (const float*)d_in[12];
    float* out = (float*)d_out;

    rnn_fused_kernel<<<NBLK, NTHR>>>(x, Wih1, Whh1, bih1, bhh1,
                                     Wih2, Whh2, bih2, bhh2,
                                     Wfc1, bfc1, Wfc2, bfc2, out);
}